// round 8
// baseline (speedup 1.0000x reference)
#include <cuda_runtime.h>
#include <math.h>
#include <stdint.h>

#define NLEV 16
#define TBITS 19
#define TMASK ((1u << TBITS) - 1u)
#define NS 128
#define NRAYS 4096

#define P1 2654435761u
#define P2 805459861u

struct Consts { float cell[NLEV]; float inv[NLEV]; };

__global__ __launch_bounds__(128)
void ngp_kernel(const float* __restrict__ rays,
                const float* __restrict__ t_rand,
                const float* __restrict__ tables,
                float* __restrict__ out,
                Consts cst)
{
    const int n = blockIdx.x;
    const int s = threadIdx.x;

    const float* ray = rays + n * 6;
    const float dirx = ray[0], diry = ray[1], dirz = ray[2];
    const float ox   = ray[3], oy   = ray[4], oz   = ray[5];

    const float step = 4.0f / 127.0f;   // (FAR-NEAR)/(NUM_SAMPLE-1)
    const float t    = 2.0f + s * step;

    const float px = ox + dirx * t;
    const float py = oy + diry * t;
    const float pz = oz + dirz * t;
    const float pxb = px + 8.0f;
    const float pyb = py + 8.0f;
    const float pzb = pz + 8.0f;

    const size_t pt = (size_t)n * NS + s;
    float2* outp2 = reinterpret_cast<float2*>(out) + pt * 16;

    // hoisted: stale values are always multiplied by wxe==0 when not loaded
    float2 e[2][4];
    #pragma unroll
    for (int k = 0; k < 2; ++k)
        #pragma unroll
        for (int c = 0; c < 4; ++c)
            e[k][c] = make_float2(0.0f, 0.0f);

    // ---- enc_pts : 16 levels; batch pairs (ip, ip+8) = coarse + fine ----
    #pragma unroll
    for (int ip = 0; ip < 8; ++ip) {
        unsigned a[2][4];
        float4   q[2][4];
        float    wyz[2][4];
        float    wx0v[2], wOv[2], wx1odd[2];

        // Phase 1: indices + issue ALL primary gathers (8x LDG.128 in flight)
        #pragma unroll
        for (int k = 0; k < 2; ++k) {
            const int i = ip + k * 8;    // level pairing: coarse + fine
            const float cell = cst.cell[i];
            const float inv  = cst.inv[i];

            const float fx = floorf(pxb * inv);
            const float fy = floorf(pyb * inv);
            const float fz = floorf(pzb * inv);

            const float dx = (px - (fx * cell - 8.0f)) * inv;
            const float dy = (py - (fy * cell - 8.0f)) * inv;
            const float dz = (pz - (fz * cell - 8.0f)) * inv;

            const unsigned ux0 = (unsigned)(int)fx;
            const bool oddx = (ux0 & 1u) != 0u;
            const unsigned hy0 = (unsigned)(int)fy * P1;
            const unsigned hy1 = hy0 + P1;
            const unsigned hz0 = (unsigned)(int)fz * P2;
            const unsigned hz1 = hz0 + P2;

            const float wx0 = 1.0f - dx, wx1 = dx;
            const float wy0 = 1.0f - dy, wy1 = dy;
            const float wz0 = 1.0f - dz, wz1 = dz;

            wx0v[k]   = wx0;
            wOv[k]    = oddx ? 0.0f : wx1;   // weight of "other" slot in pair
            wx1odd[k] = oddx ? wx1 : 0.0f;   // weight of the extra odd load

            wyz[k][0] = wy0 * wz0; wyz[k][1] = wy0 * wz1;
            wyz[k][2] = wy1 * wz0; wyz[k][3] = wy1 * wz1;

            const float4* tab4 = reinterpret_cast<const float4*>(tables)
                                 + ((size_t)i << (TBITS - 1));
            const float2* tab  = reinterpret_cast<const float2*>(tables)
                                 + ((size_t)i << TBITS);

            unsigned h[4];
            h[0] = hy0 ^ hz0; h[1] = hy0 ^ hz1;
            h[2] = hy1 ^ hz0; h[3] = hy1 ^ hz1;

            #pragma unroll
            for (int c = 0; c < 4; ++c) {
                a[k][c] = (ux0 ^ h[c]) & TMASK;
                q[k][c] = __ldg(tab4 + (a[k][c] >> 1));
            }
            // predicated (branchless) odd-corner loads
            const unsigned ux1 = ux0 + 1u;
            #pragma unroll
            for (int c = 0; c < 4; ++c) {
                if (oddx) {
                    const unsigned b = (ux1 ^ h[c]) & TMASK;
                    e[k][c] = __ldg(tab + b);
                }
            }
        }

        // Phase 2: consume + store each level's float2
        #pragma unroll
        for (int k = 0; k < 2; ++k) {
            const float wx0 = wx0v[k], wO = wOv[k], wxe = wx1odd[k];
            float f0 = 0.0f, f1 = 0.0f;
            #pragma unroll
            for (int c = 0; c < 4; ++c) {
                const bool ahi = (a[k][c] & 1u) != 0u;
                const float wlo = ahi ? wO  : wx0;
                const float whi = ahi ? wx0 : wO;
                const float wc  = wyz[k][c];
                f0 += wc * (wlo * q[k][c].x + whi * q[k][c].z + wxe * e[k][c].x);
                f1 += wc * (wlo * q[k][c].y + whi * q[k][c].w + wxe * e[k][c].y);
            }
            outp2[ip + k * 8] = make_float2(f0, f1);
        }
    }

    // ---- enc_dirs : [NRAYS, NS, 16] (same per ray) ----
    {
        const float x = dirx, y = diry, z = dirz;
        const float xx = x * x, yy = y * y, zz = z * z;
        const float xy = x * y, yz = y * z, xz = x * z;

        float sh[16];
        sh[0]  = 0.28209479177387814f;
        sh[1]  = -0.4886025119029199f * y;
        sh[2]  =  0.4886025119029199f * z;
        sh[3]  = -0.4886025119029199f * x;
        sh[4]  =  1.0925484305920792f * xy;
        sh[5]  = -1.0925484305920792f * yz;
        sh[6]  =  0.31539156525252005f * (2.0f * zz - xx - yy);
        sh[7]  = -1.0925484305920792f * xz;
        sh[8]  =  0.5462742152960396f * (xx - yy);
        sh[9]  = -0.5900435899266435f * y * (3.0f * xx - yy);
        sh[10] =  2.890611442640554f  * xy * z;
        sh[11] = -0.4570457994644658f * y * (4.0f * zz - xx - yy);
        sh[12] =  0.3731763325901154f * z * (2.0f * zz - 3.0f * xx - 3.0f * yy);
        sh[13] = -0.4570457994644658f * x * (4.0f * zz - xx - yy);
        sh[14] =  1.445305721320277f  * z * (xx - yy);
        sh[15] = -0.5900435899266435f * x * (xx - 3.0f * yy);

        float* outd = out + (size_t)NRAYS * NS * 32;
        float4* o4 = reinterpret_cast<float4*>(outd) + pt * 4;
        #pragma unroll
        for (int j = 0; j < 4; ++j) {
            o4[j] = make_float4(sh[4 * j], sh[4 * j + 1],
                                sh[4 * j + 2], sh[4 * j + 3]);
        }
    }

    // ---- dists : [NRAYS, NS] ----
    {
        float* outdist = out + (size_t)NRAYS * NS * (32 + 16);
        float dist;
        if (s == NS - 1) {
            dist = 1e10f;
        } else {
            const float tm1 = 2.0f + (s - 1) * step;
            const float tp1 = 2.0f + (s + 1) * step;
            const float tp2 = 2.0f + (s + 2) * step;

            const float r0 = t_rand[pt];
            const float r1 = t_rand[pt + 1];

            const float lower0 = (s == 0) ? t : 0.5f * (tm1 + t);
            const float upper0 = 0.5f * (t + tp1);           // s < 127 here
            const float tj0 = lower0 + (upper0 - lower0) * r0;

            const float lower1 = 0.5f * (t + tp1);
            const float upper1 = (s + 1 == NS - 1) ? tp1 : 0.5f * (tp1 + tp2);
            const float tj1 = lower1 + (upper1 - lower1) * r1;

            dist = tj1 - tj0;
        }
        outdist[pt] = dist;
    }
}

extern "C" void kernel_launch(void* const* d_in, const int* in_sizes, int n_in,
                              void* d_out, int out_size)
{
    (void)in_sizes; (void)n_in; (void)out_size;

    const float* rays   = (const float*)d_in[0];
    const float* t_rand = (const float*)d_in[1];
    const float* tables = (const float*)d_in[2];
    float* out = (float*)d_out;

    // Replicate reference resolution computation in double precision
    // (same libm on the same host as the reference run).
    Consts cst;
    const double bg = exp((log(2048.0) - log(16.0)) / 15.0);
    for (int i = 0; i < NLEV; ++i) {
        const double res = floor(16.0 * pow(bg, (double)i));
        cst.cell[i] = (float)(16.0 / res);
        cst.inv[i]  = (float)(res / 16.0);
    }

    ngp_kernel<<<NRAYS, NS>>>(rays, t_rand, tables, out, cst);
}

// round 9
// speedup vs baseline: 1.0050x; 1.0050x over previous
#include <cuda_runtime.h>
#include <math.h>
#include <stdint.h>

#define NLEV 16
#define TBITS 19
#define TMASK ((1u << TBITS) - 1u)
#define NS 128
#define NRAYS 4096

#define P1 2654435761u
#define P2 805459861u

struct Consts { float cell[NLEV]; float inv[NLEV]; };

__global__ __launch_bounds__(128)
void ngp_kernel(const float* __restrict__ rays,
                const float* __restrict__ t_rand,
                const float* __restrict__ tables,
                float* __restrict__ out,
                Consts cst)
{
    const int n = blockIdx.x;
    const int s = threadIdx.x;

    const float* ray = rays + n * 6;
    const float dirx = ray[0], diry = ray[1], dirz = ray[2];
    const float ox   = ray[3], oy   = ray[4], oz   = ray[5];

    const float step = 4.0f / 127.0f;   // (FAR-NEAR)/(NUM_SAMPLE-1)
    const float t    = 2.0f + s * step;

    const float px = ox + dirx * t;
    const float py = oy + diry * t;
    const float pz = oz + dirz * t;
    const float pxb = px + 8.0f;
    const float pyb = py + 8.0f;
    const float pzb = pz + 8.0f;

    const size_t pt = (size_t)n * NS + s;
    float2* outp2 = reinterpret_cast<float2*>(out) + pt * 16;

    // ---- enc_pts : 16 levels; each batch = one coarse + one fine level ----
    #pragma unroll
    for (int ip = 0; ip < 8; ++ip) {
        unsigned a[2][4];
        float4   q[2][4];
        float2   e[2][4];
        float    wyz[2][4];
        float    wx0v[2], wOv[2], wx1odd[2];

        // Phase 1: indices + issue ALL primary gathers (8x LDG.128 in flight)
        #pragma unroll
        for (int k = 0; k < 2; ++k) {
            const int i = ip + k * 8;    // coarse level (ip) + fine level (ip+8)
            const float cell = cst.cell[i];
            const float inv  = cst.inv[i];

            const float fx = floorf(pxb * inv);
            const float fy = floorf(pyb * inv);
            const float fz = floorf(pzb * inv);

            const float dx = (px - (fx * cell - 8.0f)) * inv;
            const float dy = (py - (fy * cell - 8.0f)) * inv;
            const float dz = (pz - (fz * cell - 8.0f)) * inv;

            const unsigned ux0 = (unsigned)(int)fx;
            const bool oddx = (ux0 & 1u) != 0u;
            const unsigned hy0 = (unsigned)(int)fy * P1;
            const unsigned hy1 = hy0 + P1;
            const unsigned hz0 = (unsigned)(int)fz * P2;
            const unsigned hz1 = hz0 + P2;

            const float wx0 = 1.0f - dx, wx1 = dx;
            const float wy0 = 1.0f - dy, wy1 = dy;
            const float wz0 = 1.0f - dz, wz1 = dz;

            wx0v[k]   = wx0;
            wOv[k]    = oddx ? 0.0f : wx1;   // weight of "other" slot in pair
            wx1odd[k] = oddx ? wx1 : 0.0f;   // weight of the extra odd load

            wyz[k][0] = wy0 * wz0; wyz[k][1] = wy0 * wz1;
            wyz[k][2] = wy1 * wz0; wyz[k][3] = wy1 * wz1;

            const float4* tab4 = reinterpret_cast<const float4*>(tables)
                                 + ((size_t)i << (TBITS - 1));
            const float2* tab  = reinterpret_cast<const float2*>(tables)
                                 + ((size_t)i << TBITS);

            unsigned h[4];
            h[0] = hy0 ^ hz0; h[1] = hy0 ^ hz1;
            h[2] = hy1 ^ hz0; h[3] = hy1 ^ hz1;

            #pragma unroll
            for (int c = 0; c < 4; ++c) {
                a[k][c] = (ux0 ^ h[c]) & TMASK;
                q[k][c] = __ldg(tab4 + (a[k][c] >> 1));
            }
            // predicated (branchless) odd-corner loads
            const unsigned ux1 = ux0 + 1u;
            #pragma unroll
            for (int c = 0; c < 4; ++c) {
                e[k][c] = make_float2(0.0f, 0.0f);
                if (oddx) {
                    const unsigned b = (ux1 ^ h[c]) & TMASK;
                    e[k][c] = __ldg(tab + b);
                }
            }
        }

        // Phase 2: consume, one float2 store per level
        #pragma unroll
        for (int k = 0; k < 2; ++k) {
            const float wx0 = wx0v[k], wO = wOv[k], wxe = wx1odd[k];
            float f0 = 0.0f, f1 = 0.0f;
            #pragma unroll
            for (int c = 0; c < 4; ++c) {
                const bool ahi = (a[k][c] & 1u) != 0u;
                const float wlo = ahi ? wO  : wx0;
                const float whi = ahi ? wx0 : wO;
                const float wc  = wyz[k][c];
                f0 += wc * (wlo * q[k][c].x + whi * q[k][c].z + wxe * e[k][c].x);
                f1 += wc * (wlo * q[k][c].y + whi * q[k][c].w + wxe * e[k][c].y);
            }
            outp2[ip + k * 8] = make_float2(f0, f1);
        }
    }

    // ---- enc_dirs : [NRAYS, NS, 16] (same per ray) ----
    {
        const float x = dirx, y = diry, z = dirz;
        const float xx = x * x, yy = y * y, zz = z * z;
        const float xy = x * y, yz = y * z, xz = x * z;

        float sh[16];
        sh[0]  = 0.28209479177387814f;
        sh[1]  = -0.4886025119029199f * y;
        sh[2]  =  0.4886025119029199f * z;
        sh[3]  = -0.4886025119029199f * x;
        sh[4]  =  1.0925484305920792f * xy;
        sh[5]  = -1.0925484305920792f * yz;
        sh[6]  =  0.31539156525252005f * (2.0f * zz - xx - yy);
        sh[7]  = -1.0925484305920792f * xz;
        sh[8]  =  0.5462742152960396f * (xx - yy);
        sh[9]  = -0.5900435899266435f * y * (3.0f * xx - yy);
        sh[10] =  2.890611442640554f  * xy * z;
        sh[11] = -0.4570457994644658f * y * (4.0f * zz - xx - yy);
        sh[12] =  0.3731763325901154f * z * (2.0f * zz - 3.0f * xx - 3.0f * yy);
        sh[13] = -0.4570457994644658f * x * (4.0f * zz - xx - yy);
        sh[14] =  1.445305721320277f  * z * (xx - yy);
        sh[15] = -0.5900435899266435f * x * (xx - 3.0f * yy);

        float* outd = out + (size_t)NRAYS * NS * 32;
        float4* o4 = reinterpret_cast<float4*>(outd) + pt * 4;
        #pragma unroll
        for (int j = 0; j < 4; ++j) {
            o4[j] = make_float4(sh[4 * j], sh[4 * j + 1],
                                sh[4 * j + 2], sh[4 * j + 3]);
        }
    }

    // ---- dists : [NRAYS, NS] ----
    {
        float* outdist = out + (size_t)NRAYS * NS * (32 + 16);
        float dist;
        if (s == NS - 1) {
            dist = 1e10f;
        } else {
            const float tm1 = 2.0f + (s - 1) * step;
            const float tp1 = 2.0f + (s + 1) * step;
            const float tp2 = 2.0f + (s + 2) * step;

            const float r0 = t_rand[pt];
            const float r1 = t_rand[pt + 1];

            const float lower0 = (s == 0) ? t : 0.5f * (tm1 + t);
            const float upper0 = 0.5f * (t + tp1);           // s < 127 here
            const float tj0 = lower0 + (upper0 - lower0) * r0;

            const float lower1 = 0.5f * (t + tp1);
            const float upper1 = (s + 1 == NS - 1) ? tp1 : 0.5f * (tp1 + tp2);
            const float tj1 = lower1 + (upper1 - lower1) * r1;

            dist = tj1 - tj0;
        }
        outdist[pt] = dist;
    }
}

extern "C" void kernel_launch(void* const* d_in, const int* in_sizes, int n_in,
                              void* d_out, int out_size)
{
    (void)in_sizes; (void)n_in; (void)out_size;

    const float* rays   = (const float*)d_in[0];
    const float* t_rand = (const float*)d_in[1];
    const float* tables = (const float*)d_in[2];
    float* out = (float*)d_out;

    // Replicate reference resolution computation in double precision
    // (same libm on the same host as the reference run).
    Consts cst;
    const double bg = exp((log(2048.0) - log(16.0)) / 15.0);
    for (int i = 0; i < NLEV; ++i) {
        const double res = floor(16.0 * pow(bg, (double)i));
        cst.cell[i] = (float)(16.0 / res);
        cst.inv[i]  = (float)(res / 16.0);
    }

    ngp_kernel<<<NRAYS, NS>>>(rays, t_rand, tables, out, cst);
}

// round 10
// speedup vs baseline: 1.2169x; 1.2108x over previous
#include <cuda_runtime.h>
#include <math.h>
#include <stdint.h>

#define NLEV 16
#define TBITS 19
#define TMASK ((1u << TBITS) - 1u)
#define NS 128
#define NRAYS 4096

#define P1 2654435761u
#define P2 805459861u

struct Consts { float cell[NLEV]; float inv[NLEV]; };

__global__ __launch_bounds__(128)
void ngp_kernel(const float* __restrict__ rays,
                const float* __restrict__ t_rand,
                const float* __restrict__ tables,
                float* __restrict__ out,
                Consts cst)
{
    const int n = blockIdx.x;
    const int s = threadIdx.x;

    const float* ray = rays + n * 6;
    const float dirx = ray[0], diry = ray[1], dirz = ray[2];
    const float ox   = ray[3], oy   = ray[4], oz   = ray[5];

    const float step = 4.0f / 127.0f;   // (FAR-NEAR)/(NUM_SAMPLE-1)
    const float t    = 2.0f + s * step;

    const float px = ox + dirx * t;
    const float py = oy + diry * t;
    const float pz = oz + dirz * t;
    const float pxb = px + 8.0f;
    const float pyb = py + 8.0f;
    const float pzb = pz + 8.0f;

    const size_t pt = (size_t)n * NS + s;
    float4* outp4 = reinterpret_cast<float4*>(out) + pt * 8;

    // Batch order: alternate heavy (fine) and light (coarse) batches.
    // Batches keep adjacent level pairs (2j, 2j+1) -> contiguous float4 store.
    constexpr int ORDER[8] = {7, 0, 6, 1, 5, 2, 4, 3};

    // ---- enc_pts : 16 levels, 2 adjacent levels per batch ----
    #pragma unroll
    for (int ipi = 0; ipi < 8; ++ipi) {
        const int ip = ORDER[ipi];
        unsigned a[2][4];
        float4   q[2][4];
        float2   e[2][4];
        float    wyz[2][4];
        float    wx0v[2], wOv[2], wx1odd[2];

        // Phase 1: indices + issue ALL primary gathers (8x LDG.128 in flight)
        #pragma unroll
        for (int k = 0; k < 2; ++k) {
            const int i = ip * 2 + k;
            const float cell = cst.cell[i];
            const float inv  = cst.inv[i];

            const float fx = floorf(pxb * inv);
            const float fy = floorf(pyb * inv);
            const float fz = floorf(pzb * inv);

            const float dx = (px - (fx * cell - 8.0f)) * inv;
            const float dy = (py - (fy * cell - 8.0f)) * inv;
            const float dz = (pz - (fz * cell - 8.0f)) * inv;

            const unsigned ux0 = (unsigned)(int)fx;
            const bool oddx = (ux0 & 1u) != 0u;
            const unsigned hy0 = (unsigned)(int)fy * P1;
            const unsigned hy1 = hy0 + P1;
            const unsigned hz0 = (unsigned)(int)fz * P2;
            const unsigned hz1 = hz0 + P2;

            const float wx0 = 1.0f - dx, wx1 = dx;
            const float wy0 = 1.0f - dy, wy1 = dy;
            const float wz0 = 1.0f - dz, wz1 = dz;

            wx0v[k]   = wx0;
            wOv[k]    = oddx ? 0.0f : wx1;   // weight of "other" slot in pair
            wx1odd[k] = oddx ? wx1 : 0.0f;   // weight of the extra odd load

            wyz[k][0] = wy0 * wz0; wyz[k][1] = wy0 * wz1;
            wyz[k][2] = wy1 * wz0; wyz[k][3] = wy1 * wz1;

            const float4* tab4 = reinterpret_cast<const float4*>(tables)
                                 + ((size_t)i << (TBITS - 1));
            const float2* tab  = reinterpret_cast<const float2*>(tables)
                                 + ((size_t)i << TBITS);

            unsigned h[4];
            h[0] = hy0 ^ hz0; h[1] = hy0 ^ hz1;
            h[2] = hy1 ^ hz0; h[3] = hy1 ^ hz1;

            #pragma unroll
            for (int c = 0; c < 4; ++c) {
                a[k][c] = (ux0 ^ h[c]) & TMASK;
                q[k][c] = __ldg(tab4 + (a[k][c] >> 1));
            }
            // predicated (branchless) odd-corner loads
            const unsigned ux1 = ux0 + 1u;
            #pragma unroll
            for (int c = 0; c < 4; ++c) {
                e[k][c] = make_float2(0.0f, 0.0f);
                if (oddx) {
                    const unsigned b = (ux1 ^ h[c]) & TMASK;
                    e[k][c] = __ldg(tab + b);
                }
            }
        }

        // Phase 2: consume
        float f[4];
        #pragma unroll
        for (int k = 0; k < 2; ++k) {
            const float wx0 = wx0v[k], wO = wOv[k], wxe = wx1odd[k];
            float f0 = 0.0f, f1 = 0.0f;
            #pragma unroll
            for (int c = 0; c < 4; ++c) {
                const bool ahi = (a[k][c] & 1u) != 0u;
                const float wlo = ahi ? wO  : wx0;
                const float whi = ahi ? wx0 : wO;
                const float wc  = wyz[k][c];
                f0 += wc * (wlo * q[k][c].x + whi * q[k][c].z + wxe * e[k][c].x);
                f1 += wc * (wlo * q[k][c].y + whi * q[k][c].w + wxe * e[k][c].y);
            }
            f[2 * k]     = f0;
            f[2 * k + 1] = f1;
        }
        outp4[ip] = make_float4(f[0], f[1], f[2], f[3]);
    }

    // ---- enc_dirs : [NRAYS, NS, 16] (same per ray) ----
    {
        const float x = dirx, y = diry, z = dirz;
        const float xx = x * x, yy = y * y, zz = z * z;
        const float xy = x * y, yz = y * z, xz = x * z;

        float sh[16];
        sh[0]  = 0.28209479177387814f;
        sh[1]  = -0.4886025119029199f * y;
        sh[2]  =  0.4886025119029199f * z;
        sh[3]  = -0.4886025119029199f * x;
        sh[4]  =  1.0925484305920792f * xy;
        sh[5]  = -1.0925484305920792f * yz;
        sh[6]  =  0.31539156525252005f * (2.0f * zz - xx - yy);
        sh[7]  = -1.0925484305920792f * xz;
        sh[8]  =  0.5462742152960396f * (xx - yy);
        sh[9]  = -0.5900435899266435f * y * (3.0f * xx - yy);
        sh[10] =  2.890611442640554f  * xy * z;
        sh[11] = -0.4570457994644658f * y * (4.0f * zz - xx - yy);
        sh[12] =  0.3731763325901154f * z * (2.0f * zz - 3.0f * xx - 3.0f * yy);
        sh[13] = -0.4570457994644658f * x * (4.0f * zz - xx - yy);
        sh[14] =  1.445305721320277f  * z * (xx - yy);
        sh[15] = -0.5900435899266435f * x * (xx - 3.0f * yy);

        float* outd = out + (size_t)NRAYS * NS * 32;
        float4* o4 = reinterpret_cast<float4*>(outd) + pt * 4;
        #pragma unroll
        for (int j = 0; j < 4; ++j) {
            o4[j] = make_float4(sh[4 * j], sh[4 * j + 1],
                                sh[4 * j + 2], sh[4 * j + 3]);
        }
    }

    // ---- dists : [NRAYS, NS] ----
    {
        float* outdist = out + (size_t)NRAYS * NS * (32 + 16);
        float dist;
        if (s == NS - 1) {
            dist = 1e10f;
        } else {
            const float tm1 = 2.0f + (s - 1) * step;
            const float tp1 = 2.0f + (s + 1) * step;
            const float tp2 = 2.0f + (s + 2) * step;

            const float r0 = t_rand[pt];
            const float r1 = t_rand[pt + 1];

            const float lower0 = (s == 0) ? t : 0.5f * (tm1 + t);
            const float upper0 = 0.5f * (t + tp1);           // s < 127 here
            const float tj0 = lower0 + (upper0 - lower0) * r0;

            const float lower1 = 0.5f * (t + tp1);
            const float upper1 = (s + 1 == NS - 1) ? tp1 : 0.5f * (tp1 + tp2);
            const float tj1 = lower1 + (upper1 - lower1) * r1;

            dist = tj1 - tj0;
        }
        outdist[pt] = dist;
    }
}

extern "C" void kernel_launch(void* const* d_in, const int* in_sizes, int n_in,
                              void* d_out, int out_size)
{
    (void)in_sizes; (void)n_in; (void)out_size;

    const float* rays   = (const float*)d_in[0];
    const float* t_rand = (const float*)d_in[1];
    const float* tables = (const float*)d_in[2];
    float* out = (float*)d_out;

    // Replicate reference resolution computation in double precision
    // (same libm on the same host as the reference run).
    Consts cst;
    const double bg = exp((log(2048.0) - log(16.0)) / 15.0);
    for (int i = 0; i < NLEV; ++i) {
        const double res = floor(16.0 * pow(bg, (double)i));
        cst.cell[i] = (float)(16.0 / res);
        cst.inv[i]  = (float)(res / 16.0);
    }

    ngp_kernel<<<NRAYS, NS>>>(rays, t_rand, tables, out, cst);
}

// round 11
// speedup vs baseline: 1.2199x; 1.0024x over previous
#include <cuda_runtime.h>
#include <math.h>
#include <stdint.h>

#define NLEV 16
#define TBITS 19
#define TMASK ((1u << TBITS) - 1u)
#define NS 128
#define NRAYS 4096

#define P1 2654435761u
#define P2 805459861u

struct Consts { float cell[NLEV]; float inv[NLEV]; };

__global__ __launch_bounds__(128)
void ngp_kernel(const float* __restrict__ rays,
                const float* __restrict__ t_rand,
                const float* __restrict__ tables,
                float* __restrict__ out,
                Consts cst)
{
    const int bid  = blockIdx.x;
    const int n    = bid >> 1;        // ray index
    const int half = bid & 1;         // which half of the level batches
    const int s    = threadIdx.x;

    const float* ray = rays + n * 6;
    const float dirx = ray[0], diry = ray[1], dirz = ray[2];
    const float ox   = ray[3], oy   = ray[4], oz   = ray[5];

    const float step = 4.0f / 127.0f;   // (FAR-NEAR)/(NUM_SAMPLE-1)
    const float t    = 2.0f + s * step;

    const float px = ox + dirx * t;
    const float py = oy + diry * t;
    const float pz = oz + dirz * t;
    const float pxb = px + 8.0f;
    const float pyb = py + 8.0f;
    const float pzb = pz + 8.0f;

    const size_t pt = (size_t)n * NS + s;
    float4* outp4 = reinterpret_cast<float4*>(out) + pt * 8;

    // This block handles batches {half, half+2, half+4, half+6}
    // in heavy->light alternating order: {6+h, h, 4+h, 2+h}.
    const int ORDER[4] = {6 + half, half, 4 + half, 2 + half};

    // ---- enc_pts : 8 levels (4 batches of 2 adjacent levels) ----
    #pragma unroll
    for (int ipi = 0; ipi < 4; ++ipi) {
        const int ip = ORDER[ipi];
        unsigned a[2][4];
        float4   q[2][4];
        float2   e[2][4];
        float    wyz[2][4];
        float    wx0v[2], wOv[2], wx1odd[2];

        // Phase 1: indices + issue ALL primary gathers (8x LDG.128 in flight)
        #pragma unroll
        for (int k = 0; k < 2; ++k) {
            const int i = ip * 2 + k;
            const float cell = cst.cell[i];
            const float inv  = cst.inv[i];

            const float fx = floorf(pxb * inv);
            const float fy = floorf(pyb * inv);
            const float fz = floorf(pzb * inv);

            const float dx = (px - (fx * cell - 8.0f)) * inv;
            const float dy = (py - (fy * cell - 8.0f)) * inv;
            const float dz = (pz - (fz * cell - 8.0f)) * inv;

            const unsigned ux0 = (unsigned)(int)fx;
            const bool oddx = (ux0 & 1u) != 0u;
            const unsigned hy0 = (unsigned)(int)fy * P1;
            const unsigned hy1 = hy0 + P1;
            const unsigned hz0 = (unsigned)(int)fz * P2;
            const unsigned hz1 = hz0 + P2;

            const float wx0 = 1.0f - dx, wx1 = dx;
            const float wy0 = 1.0f - dy, wy1 = dy;
            const float wz0 = 1.0f - dz, wz1 = dz;

            wx0v[k]   = wx0;
            wOv[k]    = oddx ? 0.0f : wx1;   // weight of "other" slot in pair
            wx1odd[k] = oddx ? wx1 : 0.0f;   // weight of the extra odd load

            wyz[k][0] = wy0 * wz0; wyz[k][1] = wy0 * wz1;
            wyz[k][2] = wy1 * wz0; wyz[k][3] = wy1 * wz1;

            const float4* tab4 = reinterpret_cast<const float4*>(tables)
                                 + ((size_t)i << (TBITS - 1));
            const float2* tab  = reinterpret_cast<const float2*>(tables)
                                 + ((size_t)i << TBITS);

            unsigned h[4];
            h[0] = hy0 ^ hz0; h[1] = hy0 ^ hz1;
            h[2] = hy1 ^ hz0; h[3] = hy1 ^ hz1;

            #pragma unroll
            for (int c = 0; c < 4; ++c) {
                a[k][c] = (ux0 ^ h[c]) & TMASK;
                q[k][c] = __ldg(tab4 + (a[k][c] >> 1));
            }
            // predicated (branchless) odd-corner loads
            const unsigned ux1 = ux0 + 1u;
            #pragma unroll
            for (int c = 0; c < 4; ++c) {
                e[k][c] = make_float2(0.0f, 0.0f);
                if (oddx) {
                    const unsigned b = (ux1 ^ h[c]) & TMASK;
                    e[k][c] = __ldg(tab + b);
                }
            }
        }

        // Phase 2: consume
        float f[4];
        #pragma unroll
        for (int k = 0; k < 2; ++k) {
            const float wx0 = wx0v[k], wO = wOv[k], wxe = wx1odd[k];
            float f0 = 0.0f, f1 = 0.0f;
            #pragma unroll
            for (int c = 0; c < 4; ++c) {
                const bool ahi = (a[k][c] & 1u) != 0u;
                const float wlo = ahi ? wO  : wx0;
                const float whi = ahi ? wx0 : wO;
                const float wc  = wyz[k][c];
                f0 += wc * (wlo * q[k][c].x + whi * q[k][c].z + wxe * e[k][c].x);
                f1 += wc * (wlo * q[k][c].y + whi * q[k][c].w + wxe * e[k][c].y);
            }
            f[2 * k]     = f0;
            f[2 * k + 1] = f1;
        }
        outp4[ip] = make_float4(f[0], f[1], f[2], f[3]);
    }

    if (half) {
        // ---- enc_dirs : [NRAYS, NS, 16] (same per ray) ----
        const float x = dirx, y = diry, z = dirz;
        const float xx = x * x, yy = y * y, zz = z * z;
        const float xy = x * y, yz = y * z, xz = x * z;

        float sh[16];
        sh[0]  = 0.28209479177387814f;
        sh[1]  = -0.4886025119029199f * y;
        sh[2]  =  0.4886025119029199f * z;
        sh[3]  = -0.4886025119029199f * x;
        sh[4]  =  1.0925484305920792f * xy;
        sh[5]  = -1.0925484305920792f * yz;
        sh[6]  =  0.31539156525252005f * (2.0f * zz - xx - yy);
        sh[7]  = -1.0925484305920792f * xz;
        sh[8]  =  0.5462742152960396f * (xx - yy);
        sh[9]  = -0.5900435899266435f * y * (3.0f * xx - yy);
        sh[10] =  2.890611442640554f  * xy * z;
        sh[11] = -0.4570457994644658f * y * (4.0f * zz - xx - yy);
        sh[12] =  0.3731763325901154f * z * (2.0f * zz - 3.0f * xx - 3.0f * yy);
        sh[13] = -0.4570457994644658f * x * (4.0f * zz - xx - yy);
        sh[14] =  1.445305721320277f  * z * (xx - yy);
        sh[15] = -0.5900435899266435f * x * (xx - 3.0f * yy);

        float* outd = out + (size_t)NRAYS * NS * 32;
        float4* o4 = reinterpret_cast<float4*>(outd) + pt * 4;
        #pragma unroll
        for (int j = 0; j < 4; ++j) {
            o4[j] = make_float4(sh[4 * j], sh[4 * j + 1],
                                sh[4 * j + 2], sh[4 * j + 3]);
        }
    } else {
        // ---- dists : [NRAYS, NS] ----
        float* outdist = out + (size_t)NRAYS * NS * (32 + 16);
        float dist;
        if (s == NS - 1) {
            dist = 1e10f;
        } else {
            const float tm1 = 2.0f + (s - 1) * step;
            const float tp1 = 2.0f + (s + 1) * step;
            const float tp2 = 2.0f + (s + 2) * step;

            const float r0 = t_rand[pt];
            const float r1 = t_rand[pt + 1];

            const float lower0 = (s == 0) ? t : 0.5f * (tm1 + t);
            const float upper0 = 0.5f * (t + tp1);           // s < 127 here
            const float tj0 = lower0 + (upper0 - lower0) * r0;

            const float lower1 = 0.5f * (t + tp1);
            const float upper1 = (s + 1 == NS - 1) ? tp1 : 0.5f * (tp1 + tp2);
            const float tj1 = lower1 + (upper1 - lower1) * r1;

            dist = tj1 - tj0;
        }
        outdist[pt] = dist;
    }
}

extern "C" void kernel_launch(void* const* d_in, const int* in_sizes, int n_in,
                              void* d_out, int out_size)
{
    (void)in_sizes; (void)n_in; (void)out_size;

    const float* rays   = (const float*)d_in[0];
    const float* t_rand = (const float*)d_in[1];
    const float* tables = (const float*)d_in[2];
    float* out = (float*)d_out;

    // Replicate reference resolution computation in double precision
    // (same libm on the same host as the reference run).
    Consts cst;
    const double bg = exp((log(2048.0) - log(16.0)) / 15.0);
    for (int i = 0; i < NLEV; ++i) {
        const double res = floor(16.0 * pow(bg, (double)i));
        cst.cell[i] = (float)(16.0 / res);
        cst.inv[i]  = (float)(res / 16.0);
    }

    ngp_kernel<<<NRAYS * 2, NS>>>(rays, t_rand, tables, out, cst);
}